// round 5
// baseline (speedup 1.0000x reference)
#include <cuda_runtime.h>
#include <cuda_bf16.h>
#include <math.h>

// HSIC_1855425872455: X [2048,16] fp32 -> scalar fp32
// R5: R4 structure with hsic_finish row-coverage fix (each warp sweeps ALL rows
//     for its pairs) and safer mask constant. 3 launches total.

#define N 2048
#define F 16
#define NPAIR 120
#define TILE 64
#define NT (N / TILE)              // 32
#define NBLK (NT * (NT + 1) / 2)   // 528
#define GRID_MAIN 264              // x2 tiles each
#define TRI16(a,b) ((a)*15 - (a)*((a)-1)/2 + ((b)-(a)-1))

__device__ float  g_Xs[N * F];
__device__ float  g_A[N * F];
__device__ double g_T[NPAIR];

__device__ __forceinline__ float ex2f(float x) {
    float r; asm("ex2.approx.f32 %0, %1;" : "=f"(r) : "f"(x)); return r;
}
__device__ __forceinline__ float wred(float v) {
    v += __shfl_xor_sync(0xffffffffu, v, 16);
    v += __shfl_xor_sync(0xffffffffu, v, 8);
    v += __shfl_xor_sync(0xffffffffu, v, 4);
    v += __shfl_xor_sync(0xffffffffu, v, 2);
    v += __shfl_xor_sync(0xffffffffu, v, 1);
    return v;
}
__device__ __forceinline__ void tile_decode(int idx, int& ti, int& tj) {
    int a = 0, rem = idx;
    while (rem >= NT - a) { rem -= NT - a; a++; }
    ti = a; tj = a + rem;
}

// ---------------------------------------------------------------------------
// k1: column stats (fp32 tree) -> scale; scale X -> g_Xs; zero g_A, g_T.
// ---------------------------------------------------------------------------
__global__ void hsic_stats_scale(const float* __restrict__ X) {
    const int tid = threadIdx.x;
    const int col = tid & 15, part = tid >> 4;       // 64 partials per column
    __shared__ float shs[1024], shq[1024];
    __shared__ float s_sc[F];
    float s = 0.f, sq = 0.f;
    for (int r = part; r < N; r += 64) {
        float v = X[r * F + col];
        s += v;
        sq = fmaf(v, v, sq);
    }
    shs[tid] = s; shq[tid] = sq;
    __syncthreads();
    #pragma unroll
    for (int off = 32; off >= 1; off >>= 1) {
        if (part < off) {
            shs[tid] += shs[tid + off * 16];
            shq[tid] += shq[tid + off * 16];
        }
        __syncthreads();
    }
    if (tid < F) {
        double m1 = (double)shs[tid] / (double)N;
        double m2 = (double)shq[tid] / (double)N;
        double meanD = 2.0 * (m2 - m1 * m1);
        s_sc[tid] = (float)sqrt(1.4426950408889634 / (2.0 * meanD));
    }
    if (tid < NPAIR) g_T[tid] = 0.0;
    __syncthreads();
    const float4* X4 = (const float4*)X;
    float4* Xs4 = (float4*)g_Xs;
    float4* A4  = (float4*)g_A;
    const float4 z4 = make_float4(0.f, 0.f, 0.f, 0.f);
    for (int q = tid; q < N * F / 4; q += 1024) {
        int c0 = (q & 3) * 4;
        float4 v = X4[q];
        v.x *= s_sc[c0]; v.y *= s_sc[c0 + 1]; v.z *= s_sc[c0 + 2]; v.w *= s_sc[c0 + 3];
        Xs4[q] = v;
        A4[q] = z4;
    }
}

// ---------------------------------------------------------------------------
// k2: main. 264 blocks x 128 threads (2 CTAs/SM), 2 tiles each.
// Warp w: w_i = w>>1 picks the 32-row half (ii = I0 + 32*w_i + lane),
//          w_j = w&1 picks the 32-col half; systolic colA ring width 32.
// Strict-upper mask folded into the ex2 arg: B = (iiG<jjG) ? 0 : -1024
// => masked k == 0 exactly, so t / rowA / colA all stay consistent.
// T weight 2 downstream; A needs no self correction (i==j masked).
// t accumulators persist across both tiles; epilogue once per CTA.
// ---------------------------------------------------------------------------
__global__ __launch_bounds__(128, 2) void hsic_main() {
    const int tid = threadIdx.x;
    const int w = tid >> 5, l = tid & 31;
    const int w_i = w >> 1, w_j = w & 1;
    __shared__ float s_xj[TILE * 20];
    __shared__ float s_row[4][32][20];
    __shared__ float s_col[4][32][20];
    __shared__ float s_t[4][NPAIR];

    float t[NPAIR];
    #pragma unroll
    for (int e = 0; e < NPAIR; e++) t[e] = 0.f;

    #pragma unroll 1
    for (int rep = 0; rep < 2; rep++) {
        int ti, tj;
        tile_decode(blockIdx.x + rep * GRID_MAIN, ti, tj);
        const int I0 = ti * TILE, J0 = tj * TILE;

        for (int q = tid; q < TILE * 4; q += 128) {
            int r = q >> 2, c4 = (q & 3) << 2;
            float4 v = *(const float4*)(g_Xs + (J0 + r) * F + c4);
            *(float4*)(s_xj + r * 20 + c4) = v;
        }
        const int iiG = I0 + w_i * 32 + l;
        float xi[F];
        {
            const float4* p = (const float4*)(g_Xs + iiG * F);
            float4 a = p[0], b = p[1], c = p[2], d = p[3];
            xi[0]=a.x; xi[1]=a.y; xi[2]=a.z; xi[3]=a.w;
            xi[4]=b.x; xi[5]=b.y; xi[6]=b.z; xi[7]=b.w;
            xi[8]=c.x; xi[9]=c.y; xi[10]=c.z; xi[11]=c.w;
            xi[12]=d.x; xi[13]=d.y; xi[14]=d.z; xi[15]=d.w;
        }
        float rowA[F], colA[F];
        #pragma unroll
        for (int c = 0; c < F; c++) { rowA[c] = 0.f; colA[c] = 0.f; }
        __syncthreads();

        #pragma unroll 2
        for (int s = 0; s < 32; s++) {
            const int jl = (w_j << 5) + ((l + s) & 31);
            const int jjG = J0 + jl;
            const float B = (iiG < jjG) ? 0.f : -1024.0f;
            const float* xj = s_xj + jl * 20;
            float k[F];
            #pragma unroll
            for (int c = 0; c < F; c++) {
                float d = xi[c] - xj[c];
                float kk = ex2f(fmaf(d, -d, B));
                k[c] = kk;
                rowA[c] += kk;
                colA[c] += kk;
            }
            #pragma unroll
            for (int a = 0; a < F; a++)
                #pragma unroll
                for (int b = a + 1; b < F; b++)
                    t[TRI16(a, b)] = fmaf(k[a], k[b], t[TRI16(a, b)]);
            const int src = (l + 1) & 31;
            #pragma unroll
            for (int c = 0; c < F; c++)
                colA[c] = __shfl_sync(0xffffffffu, colA[c], src);
        }
        // lane l now holds colA for column jl = w_j*32 + l

        #pragma unroll
        for (int c4 = 0; c4 < F; c4 += 4) {
            *(float4*)(&s_row[w][l][c4]) =
                make_float4(rowA[c4], rowA[c4+1], rowA[c4+2], rowA[c4+3]);
            *(float4*)(&s_col[w][l][c4]) =
                make_float4(colA[c4], colA[c4+1], colA[c4+2], colA[c4+3]);
        }
        __syncthreads();
        for (int idx = tid; idx < TILE * F; idx += 128) {
            const int ii = idx >> 4, c = idx & 15;
            const int ib = ii >> 5, ir = ii & 31;
            float rv = s_row[ib * 2][ir][c] + s_row[ib * 2 + 1][ir][c];
            atomicAdd(&g_A[(I0 + ii) * F + c], rv);
            float cv = s_col[ib][ir][c] + s_col[ib + 2][ir][c];
            atomicAdd(&g_A[(J0 + ii) * F + c], cv);
        }
        // next rep's pre-step __syncthreads() fences flush reads vs s_row rewrites
    }

    // t epilogue (once per CTA)
    #pragma unroll
    for (int e = 0; e < NPAIR; e++) t[e] = wred(t[e]);
    if (l == 0) {
        #pragma unroll
        for (int e = 0; e < NPAIR; e++) s_t[w][e] = t[e];
    }
    __syncthreads();
    for (int e = tid; e < NPAIR; e += 128)
        atomicAdd(&g_T[e],
                  (double)(s_t[0][e] + s_t[1][e] + s_t[2][e] + s_t[3][e]));
}

// ---------------------------------------------------------------------------
// k3: finish. One 256-thread block: Dm + S + final combine.
// Warp w owns pairs [15w, 15w+15) and S-cols {2w, 2w+1}.
// FIX vs R4: each warp sweeps ALL staged rows (lane-strided rr*32+l), so the
// warp-level wred covers all 2048 rows for its pairs/columns.
// Row stride 17 (odd) -> lane bank addresses are a permutation, conflict-free.
// ---------------------------------------------------------------------------
__global__ __launch_bounds__(256, 1) void hsic_finish(float* __restrict__ out) {
    const int tid = threadIdx.x;
    const int w = tid >> 5, l = tid & 31;
    __shared__ float  s_rows[256 * 17];
    __shared__ double s_dm[NPAIR];
    __shared__ double s_sv[F];
    __shared__ double s_red[128];

    int aa[15], bb[15];
    {
        const int e0 = 15 * w;
        #pragma unroll
        for (int p = 0; p < 15; p++) {
            int a = 0, rem = e0 + p;
            while (rem >= 15 - a) { rem -= 15 - a; a++; }
            aa[p] = a; bb[p] = a + 1 + rem;
        }
    }

    float acc[15];
    #pragma unroll
    for (int p = 0; p < 15; p++) acc[p] = 0.f;
    float sa0 = 0.f, sa1 = 0.f;

    for (int chunk = 0; chunk < 8; chunk++) {
        __syncthreads();
        for (int idx = tid; idx < 256 * F; idx += 256) {
            int r = idx >> 4, c = idx & 15;
            s_rows[r * 17 + c] = g_A[(chunk * 256 + r) * F + c];
        }
        __syncthreads();
        #pragma unroll
        for (int rr = 0; rr < 8; rr++) {
            const float* row = s_rows + (rr * 32 + l) * 17;
            #pragma unroll
            for (int p = 0; p < 15; p++)
                acc[p] = fmaf(row[aa[p]], row[bb[p]], acc[p]);
            sa0 += row[2 * w];
            sa1 += row[2 * w + 1];
        }
    }

    #pragma unroll
    for (int p = 0; p < 15; p++) acc[p] = wred(acc[p]);
    sa0 = wred(sa0); sa1 = wred(sa1);
    if (l == 0) {
        #pragma unroll
        for (int p = 0; p < 15; p++) s_dm[15 * w + p] = (double)acc[p];
        s_sv[2 * w] = (double)sa0;
        s_sv[2 * w + 1] = (double)sa1;
    }
    __syncthreads();

    double v = 0.0;
    if (tid < NPAIR) {
        int a = 0, rem = tid;
        while (rem >= 15 - a) { rem -= 15 - a; a++; }
        int b = a + 1 + rem;
        const double n = (double)N;
        double T = 2.0 * g_T[tid];                 // strict-upper weight
        double c0 = 1.0 / (n * (n - 3.0));
        double h = c0 * (T + s_sv[a] * s_sv[b] / ((n - 1.0) * (n - 2.0))
                           - (2.0 / (n - 2.0)) * s_dm[tid]);
        v = h * h;
    }
    if (tid < 128) s_red[tid] = v;
    __syncthreads();
    #pragma unroll
    for (int off = 64; off >= 1; off >>= 1) {
        if (tid < off) s_red[tid] += s_red[tid + off];
        __syncthreads();
    }
    if (tid == 0) out[0] = (float)s_red[0];
}

extern "C" void kernel_launch(void* const* d_in, const int* in_sizes, int n_in,
                              void* d_out, int out_size) {
    const float* X = (const float*)d_in[0];
    hsic_stats_scale<<<1, 1024>>>(X);
    hsic_main<<<GRID_MAIN, 128>>>();
    hsic_finish<<<1, 256>>>((float*)d_out);
}

// round 6
// speedup vs baseline: 1.3562x; 1.3562x over previous
#include <cuda_runtime.h>
#include <cuda_bf16.h>
#include <math.h>

// HSIC_1855425872455: X [2048,16] fp32 -> scalar fp32
// R6: 3 launches. Stats -> per-block partials (wide grid). Main reads raw X
// (scale folded into staging), stride-17 conflict-free smem, DIAG-templated
// mask, t persists across 2 tiles/CTA. Finish: warp-owns-all-pairs register
// accumulation, no smem staging.

#define N 2048
#define F 16
#define NPAIR 120
#define TILE 64
#define NT (N / TILE)              // 32
#define NBLK (NT * (NT + 1) / 2)   // 528
#define GRID_MAIN 264              // x2 tiles each
#define TRI16(a,b) ((a)*15 - (a)*((a)-1)/2 + ((b)-(a)-1))

__device__ float  g_A[N * F];
__device__ float  g_ps[32 * F];    // per-block column sums
__device__ float  g_pq[32 * F];    // per-block column sums of squares
__device__ double g_T[NPAIR];

__device__ __forceinline__ float ex2f(float x) {
    float r; asm("ex2.approx.f32 %0, %1;" : "=f"(r) : "f"(x)); return r;
}
__device__ __forceinline__ float wred(float v) {
    v += __shfl_xor_sync(0xffffffffu, v, 16);
    v += __shfl_xor_sync(0xffffffffu, v, 8);
    v += __shfl_xor_sync(0xffffffffu, v, 4);
    v += __shfl_xor_sync(0xffffffffu, v, 2);
    v += __shfl_xor_sync(0xffffffffu, v, 1);
    return v;
}
__device__ __forceinline__ void tile_decode(int idx, int& ti, int& tj) {
    int a = 0, rem = idx;
    while (rem >= NT - a) { rem -= NT - a; a++; }
    ti = a; tj = a + rem;
}

// ---------------------------------------------------------------------------
// k1: grid 32 x 256. Block b: column partial sums for rows [64b, 64b+64),
// zero its slice of g_A; block 0 zeroes g_T.
// ---------------------------------------------------------------------------
__global__ void hsic_stats(const float* __restrict__ X) {
    const int b = blockIdx.x, tid = threadIdx.x;
    const int col = tid & 15, part = tid >> 4;       // 16 partials per column
    __shared__ float shs[256], shq[256];
    float s = 0.f, q = 0.f;
    for (int r = part; r < TILE; r += 16) {
        float v = X[(b * TILE + r) * F + col];
        s += v;
        q = fmaf(v, v, q);
    }
    shs[tid] = s; shq[tid] = q;
    __syncthreads();
    #pragma unroll
    for (int off = 8; off >= 1; off >>= 1) {
        if (part < off) {
            shs[tid] += shs[tid + off * 16];
            shq[tid] += shq[tid + off * 16];
        }
        __syncthreads();
    }
    if (tid < F) {
        g_ps[b * F + tid] = shs[tid];
        g_pq[b * F + tid] = shq[tid];
    }
    // zero A slice: 64*16 floats = 256 float4
    float4* A4 = (float4*)g_A;
    if (tid < 256) A4[b * 256 + tid] = make_float4(0.f, 0.f, 0.f, 0.f);
    if (b == 0 && tid < NPAIR) g_T[tid] = 0.0;
}

// ---------------------------------------------------------------------------
// k2 inner: 32-step systolic sweep over one 64x64 tile half-pair.
// DIAG=true applies strict-upper mask via B in the ex2 arg (k==0 exactly).
// ---------------------------------------------------------------------------
template <bool DIAG>
__device__ __forceinline__ void tile_sweep(
    const float* __restrict__ s_xj, const float xi[F],
    float rowA[F], float colA[F], float t[NPAIR],
    int il, int w_j, int l)
{
    #pragma unroll 2
    for (int s = 0; s < 32; s++) {
        const int jl = (w_j << 5) + ((l + s) & 31);
        const float B = DIAG ? ((il < jl) ? 0.f : -1024.0f) : 0.f;
        const float* xj = s_xj + jl * 17;
        float k[F];
        #pragma unroll
        for (int c = 0; c < F; c++) {
            float d = xi[c] - xj[c];
            float kk = ex2f(fmaf(d, -d, B));
            k[c] = kk;
            rowA[c] += kk;
            colA[c] += kk;
        }
        #pragma unroll
        for (int a = 0; a < F; a++)
            #pragma unroll
            for (int b = a + 1; b < F; b++)
                t[TRI16(a, b)] = fmaf(k[a], k[b], t[TRI16(a, b)]);
        const int src = (l + 1) & 31;
        #pragma unroll
        for (int c = 0; c < F; c++)
            colA[c] = __shfl_sync(0xffffffffu, colA[c], src);
    }
}

// ---------------------------------------------------------------------------
// k2: main. 264 blocks x 128 threads (2 CTAs/SM), 2 tiles each.
// Reads raw X; scale applied during staging. Stride-17 smem (conflict-free).
// Strict i<j counting: T weight 2 downstream, A needs no self-correction.
// ---------------------------------------------------------------------------
__global__ __launch_bounds__(128, 2) void hsic_main(const float* __restrict__ X) {
    const int tid = threadIdx.x;
    const int w = tid >> 5, l = tid & 31;
    const int w_i = w >> 1, w_j = w & 1;
    __shared__ float s_sc[F];
    __shared__ float s_xj[TILE * 17];
    __shared__ float s_row[4][32][17];
    __shared__ float s_col[4][32][17];
    __shared__ float s_t[4][NPAIR];

    // per-CTA scale from k1 partials
    if (tid < F) {
        float s = 0.f, q = 0.f;
        #pragma unroll 4
        for (int b = 0; b < 32; b++) { s += g_ps[b * F + tid]; q += g_pq[b * F + tid]; }
        float m1 = s * (1.f / N), m2 = q * (1.f / N);
        float meanD = 2.f * (m2 - m1 * m1);
        s_sc[tid] = sqrtf(1.4426950408889634f / (2.f * meanD));
    }
    __syncthreads();

    float t[NPAIR];
    #pragma unroll
    for (int e = 0; e < NPAIR; e++) t[e] = 0.f;

    #pragma unroll 1
    for (int rep = 0; rep < 2; rep++) {
        int ti, tj;
        tile_decode(blockIdx.x + rep * GRID_MAIN, ti, tj);
        const int I0 = ti * TILE, J0 = tj * TILE;
        const bool diag = (ti == tj);

        // stage J tile (scaled) into stride-17 smem
        for (int q = tid; q < TILE * F; q += 128) {
            int r = q >> 4, c = q & 15;
            s_xj[r * 17 + c] = X[(J0 + r) * F + c] * s_sc[c];
        }
        const int il = (w_i << 5) + l;
        const int iiG = I0 + il;
        float xi[F];
        {
            const float4* p = (const float4*)(X + iiG * F);
            float4 a = p[0], b = p[1], c = p[2], d = p[3];
            xi[0]=a.x; xi[1]=a.y; xi[2]=a.z; xi[3]=a.w;
            xi[4]=b.x; xi[5]=b.y; xi[6]=b.z; xi[7]=b.w;
            xi[8]=c.x; xi[9]=c.y; xi[10]=c.z; xi[11]=c.w;
            xi[12]=d.x; xi[13]=d.y; xi[14]=d.z; xi[15]=d.w;
            #pragma unroll
            for (int cc = 0; cc < F; cc++) xi[cc] *= s_sc[cc];
        }
        float rowA[F], colA[F];
        #pragma unroll
        for (int c = 0; c < F; c++) { rowA[c] = 0.f; colA[c] = 0.f; }
        __syncthreads();

        if (diag) tile_sweep<true >(s_xj, xi, rowA, colA, t, il, w_j, l);
        else      tile_sweep<false>(s_xj, xi, rowA, colA, t, il, w_j, l);
        // lane l now holds colA for column jl = w_j*32 + l

        #pragma unroll
        for (int c = 0; c < F; c++) {
            s_row[w][l][c] = rowA[c];
            s_col[w][l][c] = colA[c];
        }
        __syncthreads();
        for (int idx = tid; idx < TILE * F; idx += 128) {
            const int ii = idx >> 4, c = idx & 15;
            const int ib = ii >> 5, ir = ii & 31;
            float rv = s_row[ib * 2][ir][c] + s_row[ib * 2 + 1][ir][c];
            atomicAdd(&g_A[(I0 + ii) * F + c], rv);
            float cv = s_col[ib][ir][c] + s_col[ib + 2][ir][c];
            atomicAdd(&g_A[(J0 + ii) * F + c], cv);
        }
        __syncthreads();   // protect s_xj/s_row rewrite in next rep
    }

    // t epilogue (once per CTA)
    #pragma unroll
    for (int e = 0; e < NPAIR; e++) t[e] = wred(t[e]);
    if (l == 0) {
        #pragma unroll
        for (int e = 0; e < NPAIR; e++) s_t[w][e] = t[e];
    }
    __syncthreads();
    for (int e = tid; e < NPAIR; e += 128)
        atomicAdd(&g_T[e],
                  (double)(s_t[0][e] + s_t[1][e] + s_t[2][e] + s_t[3][e]));
}

// ---------------------------------------------------------------------------
// k3: finish. 1 block x 256 threads (8 warps). Warp w owns ALL 120 pairs over
// rows [256w, 256w+256): register accumulators, coalesced LDG, one wred pass.
// Then fp64 combine of h over strict upper triangle; fp32 scalar out.
// ---------------------------------------------------------------------------
__global__ __launch_bounds__(256, 1) void hsic_finish(float* __restrict__ out) {
    const int tid = threadIdx.x;
    const int w = tid >> 5, l = tid & 31;
    __shared__ float  s_dm8[8][NPAIR];
    __shared__ float  s_sv8[8][F];
    __shared__ double s_svd[F];
    __shared__ double s_red[128];

    float acc[NPAIR], sv[F];
    #pragma unroll
    for (int e = 0; e < NPAIR; e++) acc[e] = 0.f;
    #pragma unroll
    for (int c = 0; c < F; c++) sv[c] = 0.f;

    #pragma unroll 1
    for (int it = 0; it < 8; it++) {
        const int r = w * 256 + it * 32 + l;
        const float4* p = (const float4*)(g_A + r * F);
        float4 a = p[0], b = p[1], c = p[2], d = p[3];
        float rv[F] = {a.x,a.y,a.z,a.w, b.x,b.y,b.z,b.w,
                       c.x,c.y,c.z,c.w, d.x,d.y,d.z,d.w};
        #pragma unroll
        for (int aa = 0; aa < F; aa++) {
            sv[aa] += rv[aa];
            #pragma unroll
            for (int bb = aa + 1; bb < F; bb++)
                acc[TRI16(aa, bb)] = fmaf(rv[aa], rv[bb], acc[TRI16(aa, bb)]);
        }
    }
    #pragma unroll
    for (int e = 0; e < NPAIR; e++) acc[e] = wred(acc[e]);
    #pragma unroll
    for (int c = 0; c < F; c++) sv[c] = wred(sv[c]);
    if (l == 0) {
        #pragma unroll
        for (int e = 0; e < NPAIR; e++) s_dm8[w][e] = acc[e];
        #pragma unroll
        for (int c = 0; c < F; c++) s_sv8[w][c] = sv[c];
    }
    __syncthreads();
    if (tid < F) {
        double s = 0.0;
        #pragma unroll
        for (int ww = 0; ww < 8; ww++) s += (double)s_sv8[ww][tid];
        s_svd[tid] = s;
    }
    __syncthreads();

    double v = 0.0;
    if (tid < NPAIR) {
        int a = 0, rem = tid;
        while (rem >= 15 - a) { rem -= 15 - a; a++; }
        int b = a + 1 + rem;
        double dm = 0.0;
        #pragma unroll
        for (int ww = 0; ww < 8; ww++) dm += (double)s_dm8[ww][tid];
        const double n = (double)N;
        double T = 2.0 * g_T[tid];                 // strict-upper weight
        double c0 = 1.0 / (n * (n - 3.0));
        double h = c0 * (T + s_svd[a] * s_svd[b] / ((n - 1.0) * (n - 2.0))
                           - (2.0 / (n - 2.0)) * dm);
        v = h * h;
    }
    if (tid < 128) s_red[tid] = v;
    __syncthreads();
    #pragma unroll
    for (int off = 64; off >= 1; off >>= 1) {
        if (tid < off) s_red[tid] += s_red[tid + off];
        __syncthreads();
    }
    if (tid == 0) out[0] = (float)s_red[0];
}

extern "C" void kernel_launch(void* const* d_in, const int* in_sizes, int n_in,
                              void* d_out, int out_size) {
    const float* X = (const float*)d_in[0];
    hsic_stats<<<32, 256>>>(X);
    hsic_main<<<GRID_MAIN, 128>>>(X);
    hsic_finish<<<1, 256>>>((float*)d_out);
}